// round 14
// baseline (speedup 1.0000x reference)
#include <cuda_runtime.h>
#include <cuda_fp16.h>
#include <cstdint>

#define S_LEN 1024
#define BATCH 4
#define HID   1024
#define NHEAD 16
#define HDIM  64
#define NH    (BATCH*NHEAD)     // 64 heads
#define MTOT  (S_LEN*BATCH)     // 4096
#define NTOT  (3*HID)           // 3072 (q|k|v stacked)
#define LOG2E 1.4426950408889634f

// fp16 single operands everywhere
__device__ unsigned short g_Ah[MTOT*HID];
__device__ unsigned short g_Wh[NTOT*HID];
// projections: q,k [head][s][d]; v [head][d][s] (transposed)
__device__ unsigned short g_qh[NH*S_LEN*HDIM];
__device__ unsigned short g_kh[NH*S_LEN*HDIM];
__device__ unsigned short g_vh[NH*S_LEN*HDIM];
// producer->consumer column-tile counters (24 = 3 tensors x 8 head-pairs)
__device__ unsigned int g_cnt[24];

// ---------------- helpers ----------------
__device__ __forceinline__ uint32_t smem_u32(const void* p) {
    uint32_t a;
    asm("{ .reg .u64 t; cvta.to.shared.u64 t, %1; cvt.u32.u64 %0, t; }" : "=r"(a) : "l"(p));
    return a;
}
__device__ __forceinline__ void mma16816(float* c, const uint32_t* a, const uint32_t* b) {
    asm volatile("mma.sync.aligned.m16n8k16.row.col.f32.f16.f16.f32 "
        "{%0,%1,%2,%3},{%4,%5,%6,%7},{%8,%9},{%0,%1,%2,%3};"
        : "+f"(c[0]), "+f"(c[1]), "+f"(c[2]), "+f"(c[3])
        : "r"(a[0]), "r"(a[1]), "r"(a[2]), "r"(a[3]), "r"(b[0]), "r"(b[1]));
}
__device__ __forceinline__ void ldsm_x4(uint32_t& r0, uint32_t& r1, uint32_t& r2,
                                        uint32_t& r3, uint32_t addr) {
    asm volatile("ldmatrix.sync.aligned.m8n8.x4.shared.b16 {%0,%1,%2,%3}, [%4];"
        : "=r"(r0), "=r"(r1), "=r"(r2), "=r"(r3) : "r"(addr));
}
#define CP_ASYNC16(dst, src) \
    asm volatile("cp.async.cg.shared.global [%0], [%1], 16;" :: "r"(dst), "l"(src))
#define CP_COMMIT asm volatile("cp.async.commit_group;" ::: "memory")
#define CP_WAIT0  asm volatile("cp.async.wait_group 0;" ::: "memory")

__device__ __forceinline__ uint32_t pack2h(float x, float y) {
    __half2 h = __floats2half2_rn(x, y);
    return *(uint32_t*)&h;
}
__device__ __forceinline__ uint32_t ex2_h2(uint32_t s) {
    uint32_t p;
    asm("ex2.approx.f16x2 %0, %1;" : "=r"(p) : "r"(s));
    return p;
}
__device__ __forceinline__ uint32_t hadd2u(uint32_t a, uint32_t b) {
    uint32_t r;
    asm("add.rn.f16x2 %0, %1, %2;" : "=r"(r) : "r"(a), "r"(b));
    return r;
}
__device__ __forceinline__ float h2sum(uint32_t v) {
    __half2 h = *(__half2*)&v;
    return __half2float(__low2half(h)) + __half2float(__high2half(h));
}

// ---------------- conversion + counter reset ----------------
__global__ __launch_bounds__(256)
void cvt_all(const float* __restrict__ hs, const float* __restrict__ Wq,
             const float* __restrict__ Wk, const float* __restrict__ Wv)
{
    const int bid = blockIdx.x;
    if (bid == 0 && threadIdx.x < 24) g_cnt[threadIdx.x] = 0u;

    const float* src;
    unsigned short* dst;
    size_t off;
    if (bid < 4096) {
        src = hs; dst = g_Ah;
        off = (size_t)bid * 1024 + threadIdx.x * 4;
    } else {
        int w  = (bid - 4096) >> 10;
        int lb = (bid - 4096) & 1023;
        src = (w == 0) ? Wq : ((w == 1) ? Wk : Wv);
        dst = g_Wh + (size_t)w * HID * HID;
        off = (size_t)lb * 1024 + threadIdx.x * 4;
    }
    float4 x = *(const float4*)(src + off);
    ushort4 h;
    h.x = __half_as_ushort(__float2half_rn(x.x));
    h.y = __half_as_ushort(__float2half_rn(x.y));
    h.z = __half_as_ushort(__float2half_rn(x.z));
    h.w = __half_as_ushort(__float2half_rn(x.w));
    *(ushort4*)(dst + off) = h;
}

// ================= fused QKV GEMM + flash attention =================
// Barriers halved vs R13: producer BK=64 (16 chunks), consumer 2 key-tiles
// per stage (8 barriers). Math identical to R13.
#define KST2 72                       // row stride (ushorts) for 64-col tiles
#define WOFF2 (128*KST2)              // W offset within producer stage
#define QKV_STAGE2 (2*128*KST2)       // 18432 ushorts = 36864 B
#define MST 130                       // V-transpose tile stride (ushorts)
#define VST 136                       // consumer V stride (64 rows x 128 keys)
#define VOFF (128*KST2)               // V offset within consumer stage (ushorts)
#define ATT_STAGE2 (128*KST2 + 64*VST)  // 9216+8704 = 17920 ushorts = 35840 B
#define FUSED_SMEM (2*ATT_STAGE2*2 + 2048)   // 73728 + 2048 = 75776 B

__global__ __launch_bounds__(256, 2)
void fused_qkv_attn(const float* __restrict__ bq, const float* __restrict__ bk,
                    const float* __restrict__ bv, const float* __restrict__ mask,
                    float* __restrict__ out)
{
    extern __shared__ unsigned short smq[];
    const int tid = threadIdx.x, lane = tid & 31, wid = tid >> 5;
    const int g = lane >> 2, tg = lane & 3;
    const uint32_t sbase = smem_u32(smq);

    if (blockIdx.x < 768) {
        // ======== producer: one 128x128 QKV tile, BK=64 ========
        const int p  = blockIdx.x;
        const int hp = p / 96, t = (p % 96) / 32, my = p % 32;
        const int cx = t * 8 + hp;
        const int m0 = my * 128;
        const int c0 = t * 1024 + hp * 128;
        const int wm = wid >> 2, wn = wid & 3;

        float acc[4][4][4];
#pragma unroll
        for (int i = 0; i < 4; i++)
#pragma unroll
            for (int j = 0; j < 4; j++)
#pragma unroll
                for (int k = 0; k < 4; k++) acc[i][j][k] = 0.f;

        // loader: threads 0-127 -> A row tid; 128-255 -> W row tid-128; 128B each
        const int prow = tid & 127;
        const unsigned short* gsrc = (tid < 128)
            ? g_Ah + (size_t)(m0 + prow) * HID
            : g_Wh + (size_t)(c0 + prow) * HID;
        const uint32_t dbase = ((tid < 128) ? 0u : (uint32_t)WOFF2 * 2)
                             + (uint32_t)prow * KST2 * 2;

        const int aRow = wm * 64 + (lane & 15);
        const int aK   = (lane >> 4) * 8;
        const int bRow = wn * 32 + (lane & 7) + ((lane >> 4) << 3);
        const int bK   = ((lane >> 3) & 1) * 8;

#define QKV_ISSUE(CH, STG) do { \
    const unsigned short* s_ = gsrc + (CH) * 64; \
    uint32_t d_ = sbase + (uint32_t)(STG) * QKV_STAGE2 * 2 + dbase; \
    CP_ASYNC16(d_,       s_);       CP_ASYNC16(d_ + 16,  s_ + 8); \
    CP_ASYNC16(d_ + 32,  s_ + 16);  CP_ASYNC16(d_ + 48,  s_ + 24); \
    CP_ASYNC16(d_ + 64,  s_ + 32);  CP_ASYNC16(d_ + 80,  s_ + 40); \
    CP_ASYNC16(d_ + 96,  s_ + 48);  CP_ASYNC16(d_ + 112, s_ + 56); \
    CP_COMMIT; } while (0)

        QKV_ISSUE(0, 0);

        for (int ch = 0; ch < 16; ch++) {
            const int stg = ch & 1;
            CP_WAIT0;
            __syncthreads();
            if (ch < 15) QKV_ISSUE(ch + 1, stg ^ 1);

            const uint32_t base = sbase + (uint32_t)stg * QKV_STAGE2 * 2;
#pragma unroll
            for (int ks = 0; ks < 4; ks++) {
                uint32_t ah[4][4];
#pragma unroll
                for (int mi = 0; mi < 4; mi++) {
                    uint32_t ra = base + (uint32_t)((aRow + mi*16) * KST2 + ks*16 + aK) * 2;
                    ldsm_x4(ah[mi][0], ah[mi][1], ah[mi][2], ah[mi][3], ra);
                }
#pragma unroll
                for (int np = 0; np < 2; np++) {
                    uint32_t wh[4];
                    uint32_t rb = base + (uint32_t)(WOFF2 + (bRow + np*16) * KST2 + ks*16 + bK) * 2;
                    ldsm_x4(wh[0], wh[1], wh[2], wh[3], rb);
#pragma unroll
                    for (int j = 0; j < 2; j++) {
                        const int ni = np * 2 + j;
#pragma unroll
                        for (int mi = 0; mi < 4; mi++)
                            mma16816(acc[mi][ni], ah[mi], &wh[2*j]);
                    }
                }
            }
        }

        const float* bias = (t == 0) ? bq : ((t == 1) ? bk : bv);
        const float qsc = (t == 0) ? (0.125f * LOG2E) : 1.0f;

        if (t < 2) {
            unsigned short* outp = (t == 0) ? g_qh : g_kh;
#pragma unroll
            for (int mi = 0; mi < 4; mi++) {
#pragma unroll
                for (int ni = 0; ni < 4; ni++) {
                    int colE = c0 + wn * 32 + ni * 8 + 2 * tg;
                    int bcol = colE & 1023;
                    float b0f = bias[bcol], b1f = bias[bcol + 1];
                    int hh = (colE >> 6) & 15, dd = colE & 63;
#pragma unroll
                    for (int hr = 0; hr < 2; hr++) {
                        int row = m0 + wm * 64 + mi * 16 + g + hr * 8;
                        int s = row >> 2, b = row & 3;
                        uint32_t hv = pack2h((acc[mi][ni][hr*2+0] + b0f) * qsc,
                                             (acc[mi][ni][hr*2+1] + b1f) * qsc);
                        size_t idx = ((size_t)(b * NHEAD + hh) * S_LEN + s) * HDIM + dd;
                        *(uint32_t*)&outp[idx] = hv;
                    }
                }
            }
        } else {
            // V: transpose through smem, then coalesced [head][d][s] writes
            unsigned short* Th = smq;
            __syncthreads();
#pragma unroll
            for (int mi = 0; mi < 4; mi++) {
#pragma unroll
                for (int ni = 0; ni < 4; ni++) {
                    int col = wn * 32 + ni * 8 + 2 * tg;
                    int bcol = (c0 + col) & 1023;
                    float b0f = bias[bcol], b1f = bias[bcol + 1];
#pragma unroll
                    for (int hr = 0; hr < 2; hr++) {
                        int rloc = wm * 64 + mi * 16 + g + hr * 8;
                        Th[col * MST + rloc]       = __half_as_ushort(
                            __float2half_rn(acc[mi][ni][hr * 2 + 0] + b0f));
                        Th[(col + 1) * MST + rloc] = __half_as_ushort(
                            __float2half_rn(acc[mi][ni][hr * 2 + 1] + b1f));
                    }
                }
            }
            __syncthreads();
#pragma unroll
            for (int rep = 0; rep < 2; rep++) {
                int sid = tid + rep * 256;
                int col = sid >> 2, b = sid & 3;
                int cg = c0 + col;
                int hh = (cg >> 6) & 15, dd = cg & 63;
                size_t gb = ((size_t)(b * NHEAD + hh) * HDIM + dd) * S_LEN + (m0 >> 2);
                uint32_t uh[16];
#pragma unroll
                for (int j = 0; j < 16; j++) {
                    uh[j] = (uint32_t)Th[col * MST + (2*j) * 4 + b]
                          | ((uint32_t)Th[col * MST + (2*j + 1) * 4 + b] << 16);
                }
#pragma unroll
                for (int j = 0; j < 4; j++)
                    *(uint4*)(g_vh + gb + j * 8) = make_uint4(uh[4*j], uh[4*j+1], uh[4*j+2], uh[4*j+3]);
            }
        }

        __threadfence();
        __syncthreads();
        if (tid == 0) atomicAdd(&g_cnt[cx], 1u);

    } else {
        // ======== consumer: one attention CTA; 2 key-tiles per stage ========
        const int c  = blockIdx.x - 768;
        const int hp = c >> 6, r = c & 63;
        const int h  = 2 * hp + (r & 1);
        const int b  = (r >> 1) & 3;
        const int qt = r >> 3;
        const int n  = b * NHEAD + h;

        unsigned short* msm = smq + 2 * ATT_STAGE2;   // half mask, pre-scaled
        {
            float4 x = *(const float4*)(mask + (size_t)n * S_LEN + tid * 4);
            *(uint32_t*)&msm[tid * 4]     = pack2h(x.x * LOG2E, x.y * LOG2E);
            *(uint32_t*)&msm[tid * 4 + 2] = pack2h(x.z * LOG2E, x.w * LOG2E);
        }

        if (tid == 0) {
            while (!(*(volatile unsigned*)&g_cnt[hp]      == 32u &&
                     *(volatile unsigned*)&g_cnt[8 + hp]  == 32u &&
                     *(volatile unsigned*)&g_cnt[16 + hp] == 32u))
                __nanosleep(256);
        }
        __syncthreads();
        __threadfence();

        uint32_t aqh[4][4];
        {
            const int row = qt * 128 + wid * 16 + g;
            const unsigned short* qh = g_qh + ((size_t)n * S_LEN + row) * HDIM;
#pragma unroll
            for (int ks = 0; ks < 4; ks++) {
                int k = ks * 16 + 2 * tg;
                aqh[ks][0] = *(const uint32_t*)(qh + k);
                aqh[ks][1] = *(const uint32_t*)(qh + 8*HDIM + k);
                aqh[ks][2] = *(const uint32_t*)(qh + k + 8);
                aqh[ks][3] = *(const uint32_t*)(qh + 8*HDIM + k + 8);
            }
        }

        float oacc[8][4];
#pragma unroll
        for (int i = 0; i < 8; i++)
#pragma unroll
            for (int j = 0; j < 4; j++) oacc[i][j] = 0.f;
        float l0 = 0.f, l1 = 0.f;

        // loaders: threads 0-127 -> K key-row tid (128B); 128-255 -> V d-row
        const unsigned short* gkh = g_kh + (size_t)n * S_LEN * HDIM;
        const unsigned short* gvh = g_vh + (size_t)n * S_LEN * HDIM;
        const int krow = tid & 127;
        const int vrow = (tid & 127) >> 1, vhalf = tid & 1;
        const unsigned short* lsrc0 = (tid < 128)
            ? gkh + (size_t)krow * HDIM
            : gvh + (size_t)vrow * S_LEN + vhalf * 64;
        const uint32_t ldst = (tid < 128)
            ? (uint32_t)krow * KST2 * 2
            : (uint32_t)VOFF * 2 + (uint32_t)vrow * VST * 2 + vhalf * 128;
        // per 128-key tile: K advances by 128*HDIM, V advances by 128 (cols)
        const int lstep = (tid < 128) ? 128 * HDIM : 128;

#define ATT_ISSUE(KT2, STG) do { \
    const unsigned short* s_ = lsrc0 + (size_t)(KT2) * lstep; \
    uint32_t d_ = sbase + (uint32_t)(STG) * ATT_STAGE2 * 2 + ldst; \
    CP_ASYNC16(d_,       s_);       CP_ASYNC16(d_ + 16,  s_ + 8); \
    CP_ASYNC16(d_ + 32,  s_ + 16);  CP_ASYNC16(d_ + 48,  s_ + 24); \
    CP_ASYNC16(d_ + 64,  s_ + 32);  CP_ASYNC16(d_ + 80,  s_ + 40); \
    CP_ASYNC16(d_ + 96,  s_ + 48);  CP_ASYNC16(d_ + 112, s_ + 56); \
    CP_COMMIT; } while (0)

        const int bRow = (lane & 7) + ((lane >> 4) << 3);
        const int bK   = ((lane >> 3) & 1) * 8;

        ATT_ISSUE(0, 0);

        for (int kt2 = 0; kt2 < 8; kt2++) {
            const int stg = kt2 & 1;
            CP_WAIT0;
            __syncthreads();
            if (kt2 < 7) ATT_ISSUE(kt2 + 1, stg ^ 1);

            const uint32_t base = sbase + (uint32_t)stg * ATT_STAGE2 * 2;

#pragma unroll
            for (int s2 = 0; s2 < 2; s2++) {
                float sacc[8][4];
#pragma unroll
                for (int i = 0; i < 8; i++)
#pragma unroll
                    for (int j = 0; j < 4; j++) sacc[i][j] = 0.f;

#pragma unroll
                for (int ks = 0; ks < 4; ks++) {
#pragma unroll
                    for (int np = 0; np < 4; np++) {
                        uint32_t kh[4];
                        uint32_t rb = base + (uint32_t)((s2*64 + np*16 + bRow) * KST2
                                                        + ks*16 + bK) * 2;
                        ldsm_x4(kh[0], kh[1], kh[2], kh[3], rb);
                        mma16816(sacc[np*2],   aqh[ks], &kh[0]);
                        mma16816(sacc[np*2+1], aqh[ks], &kh[2]);
                    }
                }

                // half2 softmax: p = ex2(s + mask')
                uint32_t ph[8][2];
                uint32_t ls0 = 0u, ls1 = 0u;
                const int mko = kt2 * 128 + s2 * 64;
#pragma unroll
                for (int ni = 0; ni < 8; ni++) {
                    uint32_t mk2 = *(const uint32_t*)&msm[mko + ni*8 + 2*tg];
                    uint32_t s01 = hadd2u(pack2h(sacc[ni][0], sacc[ni][1]), mk2);
                    uint32_t s23 = hadd2u(pack2h(sacc[ni][2], sacc[ni][3]), mk2);
                    uint32_t p01 = ex2_h2(s01);
                    uint32_t p23 = ex2_h2(s23);
                    ph[ni][0] = p01;
                    ph[ni][1] = p23;
                    ls0 = hadd2u(ls0, p01);
                    ls1 = hadd2u(ls1, p23);
                }
                l0 += h2sum(ls0);
                l1 += h2sum(ls1);

                // AV: P half2 registers feed the MMA directly
#pragma unroll
                for (int kk = 0; kk < 4; kk++) {
                    uint32_t pah[4];
                    pah[0] = ph[2*kk][0];
                    pah[1] = ph[2*kk][1];
                    pah[2] = ph[2*kk+1][0];
                    pah[3] = ph[2*kk+1][1];
#pragma unroll
                    for (int np = 0; np < 4; np++) {
                        uint32_t vh[4];
                        uint32_t rb = base + (uint32_t)(VOFF + (np*16 + bRow) * VST
                                                        + s2*64 + kk*16 + bK) * 2;
                        ldsm_x4(vh[0], vh[1], vh[2], vh[3], rb);
                        mma16816(oacc[np*2],   pah, &vh[0]);
                        mma16816(oacc[np*2+1], pah, &vh[2]);
                    }
                }
            }
        }

        // one-time denominator reduction across the quad
        l0 += __shfl_xor_sync(0xffffffffu, l0, 1);
        l0 += __shfl_xor_sync(0xffffffffu, l0, 2);
        l1 += __shfl_xor_sync(0xffffffffu, l1, 1);
        l1 += __shfl_xor_sync(0xffffffffu, l1, 2);

        const float inv0 = 1.f / l0, inv1 = 1.f / l1;
        const int row0 = qt * 128 + wid * 16 + g;
#pragma unroll
        for (int ni = 0; ni < 8; ni++) {
            int d = ni * 8 + 2 * tg;
            float2 v0 = make_float2(oacc[ni][0] * inv0, oacc[ni][1] * inv0);
            float2 v1 = make_float2(oacc[ni][2] * inv1, oacc[ni][3] * inv1);
            *(float2*)(out + (size_t)row0 * (BATCH*HID) + b * HID + h * HDIM + d) = v0;
            *(float2*)(out + (size_t)(row0 + 8) * (BATCH*HID) + b * HID + h * HDIM + d) = v1;
        }
    }
}

// ------------------------------------------------------------------
extern "C" void kernel_launch(void* const* d_in, const int* in_sizes, int n_in,
                              void* d_out, int out_size)
{
    const float* hs   = (const float*)d_in[0];
    const float* mask = (const float*)d_in[1];
    const float* Wq   = (const float*)d_in[2];
    const float* bq   = (const float*)d_in[3];
    const float* Wk   = (const float*)d_in[4];
    const float* bk   = (const float*)d_in[5];
    const float* Wv   = (const float*)d_in[6];
    const float* bv   = (const float*)d_in[7];
    float* out = (float*)d_out;

    cvt_all<<<7168, 256>>>(hs, Wq, Wk, Wv);

    cudaFuncSetAttribute(fused_qkv_attn, cudaFuncAttributeMaxDynamicSharedMemorySize,
                         FUSED_SMEM);
    fused_qkv_attn<<<1280, 256, FUSED_SMEM>>>(bq, bk, bv, mask, out);
}

// round 15
// speedup vs baseline: 1.2909x; 1.2909x over previous
#include <cuda_runtime.h>
#include <cuda_fp16.h>
#include <cstdint>

#define S_LEN 1024
#define BATCH 4
#define HID   1024
#define NHEAD 16
#define HDIM  64
#define NH    (BATCH*NHEAD)     // 64 heads
#define MTOT  (S_LEN*BATCH)     // 4096
#define NTOT  (3*HID)           // 3072 (q|k|v stacked)
#define LOG2E 1.4426950408889634f

// fp16 single operands everywhere
__device__ unsigned short g_Ah[MTOT*HID];
__device__ unsigned short g_Wh[NTOT*HID];
// projections: q,k [head][s][d]; v [head][d][s] (transposed)
__device__ unsigned short g_qh[NH*S_LEN*HDIM];
__device__ unsigned short g_kh[NH*S_LEN*HDIM];
__device__ unsigned short g_vh[NH*S_LEN*HDIM];
// producer->consumer column-tile counters (24 = 3 tensors x 8 head-pairs)
__device__ unsigned int g_cnt[24];

// ---------------- helpers ----------------
__device__ __forceinline__ uint32_t smem_u32(const void* p) {
    uint32_t a;
    asm("{ .reg .u64 t; cvta.to.shared.u64 t, %1; cvt.u32.u64 %0, t; }" : "=r"(a) : "l"(p));
    return a;
}
__device__ __forceinline__ void mma16816(float* c, const uint32_t* a, const uint32_t* b) {
    asm volatile("mma.sync.aligned.m16n8k16.row.col.f32.f16.f16.f32 "
        "{%0,%1,%2,%3},{%4,%5,%6,%7},{%8,%9},{%0,%1,%2,%3};"
        : "+f"(c[0]), "+f"(c[1]), "+f"(c[2]), "+f"(c[3])
        : "r"(a[0]), "r"(a[1]), "r"(a[2]), "r"(a[3]), "r"(b[0]), "r"(b[1]));
}
__device__ __forceinline__ void ldsm_x4(uint32_t& r0, uint32_t& r1, uint32_t& r2,
                                        uint32_t& r3, uint32_t addr) {
    asm volatile("ldmatrix.sync.aligned.m8n8.x4.shared.b16 {%0,%1,%2,%3}, [%4];"
        : "=r"(r0), "=r"(r1), "=r"(r2), "=r"(r3) : "r"(addr));
}
#define CP_ASYNC16(dst, src) \
    asm volatile("cp.async.cg.shared.global [%0], [%1], 16;" :: "r"(dst), "l"(src))
#define CP_COMMIT asm volatile("cp.async.commit_group;" ::: "memory")
#define CP_WAIT0  asm volatile("cp.async.wait_group 0;" ::: "memory")

__device__ __forceinline__ uint32_t pack2h(float x, float y) {
    __half2 h = __floats2half2_rn(x, y);
    return *(uint32_t*)&h;
}
__device__ __forceinline__ uint32_t ex2_h2(uint32_t s) {
    uint32_t p;
    asm("ex2.approx.f16x2 %0, %1;" : "=r"(p) : "r"(s));
    return p;
}
__device__ __forceinline__ uint32_t hadd2u(uint32_t a, uint32_t b) {
    uint32_t r;
    asm("add.rn.f16x2 %0, %1, %2;" : "=r"(r) : "r"(a), "r"(b));
    return r;
}
__device__ __forceinline__ float h2sum(uint32_t v) {
    __half2 h = *(__half2*)&v;
    return __half2float(__low2half(h)) + __half2float(__high2half(h));
}

// ---------------- conversion + counter reset ----------------
__global__ __launch_bounds__(256)
void cvt_all(const float* __restrict__ hs, const float* __restrict__ Wq,
             const float* __restrict__ Wk, const float* __restrict__ Wv)
{
    const int bid = blockIdx.x;
    if (bid == 0 && threadIdx.x < 24) g_cnt[threadIdx.x] = 0u;

    const float* src;
    unsigned short* dst;
    size_t off;
    if (bid < 4096) {
        src = hs; dst = g_Ah;
        off = (size_t)bid * 1024 + threadIdx.x * 4;
    } else {
        int w  = (bid - 4096) >> 10;
        int lb = (bid - 4096) & 1023;
        src = (w == 0) ? Wq : ((w == 1) ? Wk : Wv);
        dst = g_Wh + (size_t)w * HID * HID;
        off = (size_t)lb * 1024 + threadIdx.x * 4;
    }
    float4 x = *(const float4*)(src + off);
    ushort4 h;
    h.x = __half_as_ushort(__float2half_rn(x.x));
    h.y = __half_as_ushort(__float2half_rn(x.y));
    h.z = __half_as_ushort(__float2half_rn(x.z));
    h.w = __half_as_ushort(__float2half_rn(x.w));
    *(ushort4*)(dst + off) = h;
}

// ================= fused QKV GEMM + flash attention =================
#define GST 40
#define QKV_STAGE (2*128*GST)        // ushorts per stage (A|W)
#define MST 130                      // V-transpose tile stride (ushorts)
#define KST 72
#define ATT_STAGE (2*64*KST)         // ushorts per stage (K|V)
#define FUSED_SMEM 40960

__global__ __launch_bounds__(256, 2)
void fused_qkv_attn(const float* __restrict__ bq, const float* __restrict__ bk,
                    const float* __restrict__ bv, const float* __restrict__ mask,
                    float* __restrict__ out)
{
    extern __shared__ unsigned short smq[];
    const int tid = threadIdx.x, lane = tid & 31, wid = tid >> 5;
    const int g = lane >> 2, tg = lane & 3;
    const uint32_t sbase = smem_u32(smq);

    if (blockIdx.x < 768) {
        // ======== producer: one 128x128 QKV tile ========
        const int p  = blockIdx.x;
        const int hp = p / 96, t = (p % 96) / 32, my = p % 32;
        const int cx = t * 8 + hp;
        const int m0 = my * 128;
        const int c0 = t * 1024 + hp * 128;
        const int wm = wid >> 2, wn = wid & 3;

        float acc[4][4][4];
#pragma unroll
        for (int i = 0; i < 4; i++)
#pragma unroll
            for (int j = 0; j < 4; j++)
#pragma unroll
                for (int k = 0; k < 4; k++) acc[i][j][k] = 0.f;

        const int lrow = tid >> 1, lhalf = tid & 1;
        const unsigned short* gA0 = g_Ah + (size_t)(m0 + lrow) * HID + lhalf * 16;
        const unsigned short* gW0 = g_Wh + (size_t)(c0 + lrow) * HID + lhalf * 16;
        const uint32_t dOff = (uint32_t)(lrow * GST + lhalf * 16) * 2;

        const int aRow = wm * 64 + (lane & 15);
        const int aK   = (lane >> 4) * 8;
        const int bRow = wn * 32 + (lane & 7) + ((lane >> 4) << 3);
        const int bK   = ((lane >> 3) & 1) * 8;

#define QKV_ISSUE(CH, STG) do { \
    int k0 = (CH) * 32; \
    uint32_t dst = sbase + (uint32_t)(STG) * QKV_STAGE * 2 + dOff; \
    CP_ASYNC16(dst,                  gA0 + k0); \
    CP_ASYNC16(dst + 16,             gA0 + k0 + 8); \
    CP_ASYNC16(dst + 128*GST*2,      gW0 + k0); \
    CP_ASYNC16(dst + 128*GST*2 + 16, gW0 + k0 + 8); \
    CP_COMMIT; } while (0)

        QKV_ISSUE(0, 0);

        for (int ch = 0; ch < 32; ch++) {
            const int stg = ch & 1;
            CP_WAIT0;
            __syncthreads();
            if (ch < 31) QKV_ISSUE(ch + 1, stg ^ 1);

            const uint32_t base = sbase + (uint32_t)stg * QKV_STAGE * 2;
#pragma unroll
            for (int ks = 0; ks < 2; ks++) {
                uint32_t ah[4][4];
#pragma unroll
                for (int mi = 0; mi < 4; mi++) {
                    uint32_t ra = base + (uint32_t)((aRow + mi*16) * GST + ks*16 + aK) * 2;
                    ldsm_x4(ah[mi][0], ah[mi][1], ah[mi][2], ah[mi][3], ra);
                }
#pragma unroll
                for (int np = 0; np < 2; np++) {
                    uint32_t wh[4];
                    uint32_t rb = base + (uint32_t)(128*GST + (bRow + np*16) * GST + ks*16 + bK) * 2;
                    ldsm_x4(wh[0], wh[1], wh[2], wh[3], rb);
#pragma unroll
                    for (int j = 0; j < 2; j++) {
                        const int ni = np * 2 + j;
#pragma unroll
                        for (int mi = 0; mi < 4; mi++)
                            mma16816(acc[mi][ni], ah[mi], &wh[2*j]);
                    }
                }
            }
        }

        const float* bias = (t == 0) ? bq : ((t == 1) ? bk : bv);
        // Q carries 1/8 * log2(e) so consumer can use ex2 directly
        const float qsc = (t == 0) ? (0.125f * LOG2E) : 1.0f;

        if (t < 2) {
            unsigned short* outp = (t == 0) ? g_qh : g_kh;
#pragma unroll
            for (int mi = 0; mi < 4; mi++) {
#pragma unroll
                for (int ni = 0; ni < 4; ni++) {
                    int colE = c0 + wn * 32 + ni * 8 + 2 * tg;
                    int bcol = colE & 1023;
                    float b0f = bias[bcol], b1f = bias[bcol + 1];
                    int hh = (colE >> 6) & 15, dd = colE & 63;
#pragma unroll
                    for (int hr = 0; hr < 2; hr++) {
                        int row = m0 + wm * 64 + mi * 16 + g + hr * 8;
                        int s = row >> 2, b = row & 3;
                        uint32_t hv = pack2h((acc[mi][ni][hr*2+0] + b0f) * qsc,
                                             (acc[mi][ni][hr*2+1] + b1f) * qsc);
                        size_t idx = ((size_t)(b * NHEAD + hh) * S_LEN + s) * HDIM + dd;
                        *(uint32_t*)&outp[idx] = hv;
                    }
                }
            }
        } else {
            // V: transpose through smem, then coalesced [head][d][s] writes
            unsigned short* Th = smq;
            __syncthreads();
#pragma unroll
            for (int mi = 0; mi < 4; mi++) {
#pragma unroll
                for (int ni = 0; ni < 4; ni++) {
                    int col = wn * 32 + ni * 8 + 2 * tg;
                    int bcol = (c0 + col) & 1023;
                    float b0f = bias[bcol], b1f = bias[bcol + 1];
#pragma unroll
                    for (int hr = 0; hr < 2; hr++) {
                        int rloc = wm * 64 + mi * 16 + g + hr * 8;
                        Th[col * MST + rloc]       = __half_as_ushort(
                            __float2half_rn(acc[mi][ni][hr * 2 + 0] + b0f));
                        Th[(col + 1) * MST + rloc] = __half_as_ushort(
                            __float2half_rn(acc[mi][ni][hr * 2 + 1] + b1f));
                    }
                }
            }
            __syncthreads();
#pragma unroll
            for (int rep = 0; rep < 2; rep++) {
                int sid = tid + rep * 256;
                int col = sid >> 2, b = sid & 3;
                int cg = c0 + col;
                int hh = (cg >> 6) & 15, dd = cg & 63;
                size_t gb = ((size_t)(b * NHEAD + hh) * HDIM + dd) * S_LEN + (m0 >> 2);
                uint32_t uh[16];
#pragma unroll
                for (int j = 0; j < 16; j++) {
                    uh[j] = (uint32_t)Th[col * MST + (2*j) * 4 + b]
                          | ((uint32_t)Th[col * MST + (2*j + 1) * 4 + b] << 16);
                }
#pragma unroll
                for (int j = 0; j < 4; j++)
                    *(uint4*)(g_vh + gb + j * 8) = make_uint4(uh[4*j], uh[4*j+1], uh[4*j+2], uh[4*j+3]);
            }
        }

        // ---- release: publish this column tile ----
        __threadfence();
        __syncthreads();
        if (tid == 0) atomicAdd(&g_cnt[cx], 1u);

    } else {
        // ======== consumer: one attention CTA (head n, 128-q tile) ========
        const int c  = blockIdx.x - 768;
        const int hp = c >> 6, r = c & 63;
        const int h  = 2 * hp + (r & 1);
        const int b  = (r >> 1) & 3;
        const int qt = r >> 3;
        const int n  = b * NHEAD + h;

        // mask staged as half, pre-scaled by log2(e)
        unsigned short* msm = smq + 2 * ATT_STAGE;
        {
            float4 x = *(const float4*)(mask + (size_t)n * S_LEN + tid * 4);
            *(uint32_t*)&msm[tid * 4]     = pack2h(x.x * LOG2E, x.y * LOG2E);
            *(uint32_t*)&msm[tid * 4 + 2] = pack2h(x.z * LOG2E, x.w * LOG2E);
        }

        if (tid == 0) {
            while (!(*(volatile unsigned*)&g_cnt[hp]      == 32u &&
                     *(volatile unsigned*)&g_cnt[8 + hp]  == 32u &&
                     *(volatile unsigned*)&g_cnt[16 + hp] == 32u))
                __nanosleep(256);
        }
        __syncthreads();
        __threadfence();

        uint32_t aqh[4][4];
        {
            const int row = qt * 128 + wid * 16 + g;
            const unsigned short* qh = g_qh + ((size_t)n * S_LEN + row) * HDIM;
#pragma unroll
            for (int ks = 0; ks < 4; ks++) {
                int k = ks * 16 + 2 * tg;
                aqh[ks][0] = *(const uint32_t*)(qh + k);
                aqh[ks][1] = *(const uint32_t*)(qh + 8*HDIM + k);
                aqh[ks][2] = *(const uint32_t*)(qh + k + 8);
                aqh[ks][3] = *(const uint32_t*)(qh + 8*HDIM + k + 8);
            }
        }

        float oacc[8][4];
#pragma unroll
        for (int i = 0; i < 8; i++)
#pragma unroll
            for (int j = 0; j < 4; j++) oacc[i][j] = 0.f;
        float l0 = 0.f, l1 = 0.f;

        const int lrow = tid >> 2, lseg = (tid & 3) * 2;
        const unsigned short* gkh = g_kh + (size_t)n * S_LEN * HDIM;
        const unsigned short* gvh = g_vh + (size_t)n * S_LEN * HDIM + (size_t)lrow * S_LEN;
        const uint32_t dKV = (uint32_t)(lrow * KST + lseg * 8) * 2;

#define ATT_ISSUE(KT, STG) do { \
    uint32_t dst = sbase + (uint32_t)(STG) * ATT_STAGE * 2 + dKV; \
    const unsigned short* sk = gkh + ((KT)*64 + lrow) * HDIM + lseg * 8; \
    const unsigned short* sv = gvh + (KT)*64 + lseg * 8; \
    CP_ASYNC16(dst,              sk);  CP_ASYNC16(dst + 16,              sk + 8); \
    CP_ASYNC16(dst + 64*KST*2,   sv);  CP_ASYNC16(dst + 64*KST*2 + 16,   sv + 8); \
    CP_COMMIT; } while (0)

        const int bRow = (lane & 7) + ((lane >> 4) << 3);
        const int bK   = ((lane >> 3) & 1) * 8;

        ATT_ISSUE(0, 0);

        for (int kt = 0; kt < 16; kt++) {
            const int stg = kt & 1;
            CP_WAIT0;
            __syncthreads();
            if (kt < 15) ATT_ISSUE(kt + 1, stg ^ 1);

            const uint32_t base = sbase + (uint32_t)stg * ATT_STAGE * 2;

            float sacc[8][4];
#pragma unroll
            for (int i = 0; i < 8; i++)
#pragma unroll
                for (int j = 0; j < 4; j++) sacc[i][j] = 0.f;

#pragma unroll
            for (int ks = 0; ks < 4; ks++) {
#pragma unroll
                for (int np = 0; np < 4; np++) {
                    uint32_t kh[4];
                    uint32_t rb = base + (uint32_t)((np*16 + bRow) * KST + ks*16 + bK) * 2;
                    ldsm_x4(kh[0], kh[1], kh[2], kh[3], rb);
                    mma16816(sacc[np*2],   aqh[ks], &kh[0]);
                    mma16816(sacc[np*2+1], aqh[ks], &kh[2]);
                }
            }

            // ---- fused softmax + AV: exp for row-pair kk overlaps AV step kk ----
            uint32_t ls0 = 0u, ls1 = 0u;    // half2 partial denominators
#pragma unroll
            for (int kk = 0; kk < 4; kk++) {
                const int ni0 = 2 * kk, ni1 = 2 * kk + 1;
                uint32_t pah[4];
                {
                    uint32_t mk2 = *(const uint32_t*)&msm[kt*64 + ni0*8 + 2*tg];
                    uint32_t s01 = hadd2u(pack2h(sacc[ni0][0], sacc[ni0][1]), mk2);
                    uint32_t s23 = hadd2u(pack2h(sacc[ni0][2], sacc[ni0][3]), mk2);
                    pah[0] = ex2_h2(s01);
                    pah[1] = ex2_h2(s23);
                    ls0 = hadd2u(ls0, pah[0]);
                    ls1 = hadd2u(ls1, pah[1]);
                }
                {
                    uint32_t mk2 = *(const uint32_t*)&msm[kt*64 + ni1*8 + 2*tg];
                    uint32_t s01 = hadd2u(pack2h(sacc[ni1][0], sacc[ni1][1]), mk2);
                    uint32_t s23 = hadd2u(pack2h(sacc[ni1][2], sacc[ni1][3]), mk2);
                    pah[2] = ex2_h2(s01);
                    pah[3] = ex2_h2(s23);
                    ls0 = hadd2u(ls0, pah[2]);
                    ls1 = hadd2u(ls1, pah[3]);
                }
#pragma unroll
                for (int np = 0; np < 4; np++) {
                    uint32_t vh[4];
                    uint32_t rb = base + (uint32_t)(64*KST + (np*16 + bRow) * KST + kk*16 + bK) * 2;
                    ldsm_x4(vh[0], vh[1], vh[2], vh[3], rb);
                    mma16816(oacc[np*2],   pah, &vh[0]);
                    mma16816(oacc[np*2+1], pah, &vh[2]);
                }
            }
            l0 += h2sum(ls0);
            l1 += h2sum(ls1);
        }

        // ---- one-time denominator reduction across the quad ----
        l0 += __shfl_xor_sync(0xffffffffu, l0, 1);
        l0 += __shfl_xor_sync(0xffffffffu, l0, 2);
        l1 += __shfl_xor_sync(0xffffffffu, l1, 1);
        l1 += __shfl_xor_sync(0xffffffffu, l1, 2);

        const float inv0 = 1.f / l0, inv1 = 1.f / l1;
        const int row0 = qt * 128 + wid * 16 + g;
#pragma unroll
        for (int ni = 0; ni < 8; ni++) {
            int d = ni * 8 + 2 * tg;
            float2 v0 = make_float2(oacc[ni][0] * inv0, oacc[ni][1] * inv0);
            float2 v1 = make_float2(oacc[ni][2] * inv1, oacc[ni][3] * inv1);
            *(float2*)(out + (size_t)row0 * (BATCH*HID) + b * HID + h * HDIM + d) = v0;
            *(float2*)(out + (size_t)(row0 + 8) * (BATCH*HID) + b * HID + h * HDIM + d) = v1;
        }
    }
}

// ------------------------------------------------------------------
extern "C" void kernel_launch(void* const* d_in, const int* in_sizes, int n_in,
                              void* d_out, int out_size)
{
    const float* hs   = (const float*)d_in[0];
    const float* mask = (const float*)d_in[1];
    const float* Wq   = (const float*)d_in[2];
    const float* bq   = (const float*)d_in[3];
    const float* Wk   = (const float*)d_in[4];
    const float* bk   = (const float*)d_in[5];
    const float* Wv   = (const float*)d_in[6];
    const float* bv   = (const float*)d_in[7];
    float* out = (float*)d_out;

    cvt_all<<<7168, 256>>>(hs, Wq, Wk, Wv);

    cudaFuncSetAttribute(fused_qkv_attn, cudaFuncAttributeMaxDynamicSharedMemorySize,
                         FUSED_SMEM);
    fused_qkv_attn<<<1280, 256, FUSED_SMEM>>>(bq, bk, bv, mask, out);
}

// round 16
// speedup vs baseline: 1.2961x; 1.0040x over previous
#include <cuda_runtime.h>
#include <cuda_fp16.h>
#include <cstdint>

#define S_LEN 1024
#define BATCH 4
#define HID   1024
#define NHEAD 16
#define HDIM  64
#define NH    (BATCH*NHEAD)     // 64 heads
#define MTOT  (S_LEN*BATCH)     // 4096
#define NTOT  (3*HID)           // 3072 (q|k|v stacked)
#define LOG2E 1.4426950408889634f

// fp16 single operands everywhere
__device__ unsigned short g_Ah[MTOT*HID];
__device__ unsigned short g_Wh[NTOT*HID];
// projections: q,k [head][s][d]; v [head][d][s] (transposed)
__device__ unsigned short g_qh[NH*S_LEN*HDIM];
__device__ unsigned short g_kh[NH*S_LEN*HDIM];
__device__ unsigned short g_vh[NH*S_LEN*HDIM];
// producer->consumer column-tile counters (24 = 3 tensors x 8 head-pairs)
__device__ unsigned int g_cnt[24];

// ---------------- helpers ----------------
__device__ __forceinline__ uint32_t smem_u32(const void* p) {
    uint32_t a;
    asm("{ .reg .u64 t; cvta.to.shared.u64 t, %1; cvt.u32.u64 %0, t; }" : "=r"(a) : "l"(p));
    return a;
}
__device__ __forceinline__ void mma16816(float* c, const uint32_t* a, const uint32_t* b) {
    asm volatile("mma.sync.aligned.m16n8k16.row.col.f32.f16.f16.f32 "
        "{%0,%1,%2,%3},{%4,%5,%6,%7},{%8,%9},{%0,%1,%2,%3};"
        : "+f"(c[0]), "+f"(c[1]), "+f"(c[2]), "+f"(c[3])
        : "r"(a[0]), "r"(a[1]), "r"(a[2]), "r"(a[3]), "r"(b[0]), "r"(b[1]));
}
__device__ __forceinline__ void ldsm_x4(uint32_t& r0, uint32_t& r1, uint32_t& r2,
                                        uint32_t& r3, uint32_t addr) {
    asm volatile("ldmatrix.sync.aligned.m8n8.x4.shared.b16 {%0,%1,%2,%3}, [%4];"
        : "=r"(r0), "=r"(r1), "=r"(r2), "=r"(r3) : "r"(addr));
}
#define CP_ASYNC16(dst, src) \
    asm volatile("cp.async.cg.shared.global [%0], [%1], 16;" :: "r"(dst), "l"(src))
#define CP_COMMIT asm volatile("cp.async.commit_group;" ::: "memory")
#define CP_WAIT0  asm volatile("cp.async.wait_group 0;" ::: "memory")

__device__ __forceinline__ uint32_t pack2h(float x, float y) {
    __half2 h = __floats2half2_rn(x, y);
    return *(uint32_t*)&h;
}
__device__ __forceinline__ uint32_t ex2_h2(uint32_t s) {
    uint32_t p;
    asm("ex2.approx.f16x2 %0, %1;" : "=r"(p) : "r"(s));
    return p;
}
__device__ __forceinline__ uint32_t hadd2u(uint32_t a, uint32_t b) {
    uint32_t r;
    asm("add.rn.f16x2 %0, %1, %2;" : "=r"(r) : "r"(a), "r"(b));
    return r;
}
__device__ __forceinline__ float h2sum(uint32_t v) {
    __half2 h = *(__half2*)&v;
    return __half2float(__low2half(h)) + __half2float(__high2half(h));
}
__device__ __forceinline__ ushort4 cvt4(float4 x) {
    ushort4 h;
    h.x = __half_as_ushort(__float2half_rn(x.x));
    h.y = __half_as_ushort(__float2half_rn(x.y));
    h.z = __half_as_ushort(__float2half_rn(x.z));
    h.w = __half_as_ushort(__float2half_rn(x.w));
    return h;
}

// ---------------- conversion + counter reset (wide: 4 float4 per thread) ----------------
// 7.34M floats total; grid 1792 x 256 thr x 16 floats. Layout: contiguous
// A (4.19M) then W stacked (3.15M) -> same destinations as before.
__global__ __launch_bounds__(256)
void cvt_all(const float* __restrict__ hs, const float* __restrict__ Wq,
             const float* __restrict__ Wk, const float* __restrict__ Wv)
{
    if (blockIdx.x == 0 && threadIdx.x < 24) g_cnt[threadIdx.x] = 0u;

    const size_t tix = (size_t)blockIdx.x * 256 + threadIdx.x;
    // 4 independent float4 chunks, stride 4096 elements apart within the block's span
    const size_t e0 = (size_t)blockIdx.x * 4096 + threadIdx.x * 4;
#pragma unroll
    for (int rep = 0; rep < 4; rep++) {
        size_t e = e0 + rep * 1024;                 // element index (multiple of 4)
        const float* src;
        unsigned short* dst;
        size_t off;
        if (e < (size_t)MTOT * HID) {
            src = hs; dst = g_Ah; off = e;
        } else {
            size_t w2 = e - (size_t)MTOT * HID;     // 0 .. 3*1024*1024
            int w = (int)(w2 >> 20);                // which weight matrix
            src = (w == 0) ? Wq : ((w == 1) ? Wk : Wv);
            dst = g_Wh + ((size_t)w << 20);
            off = w2 & 0xFFFFFu;
        }
        float4 x = *(const float4*)(src + off);
        *(ushort4*)(dst + off) = cvt4(x);
    }
    (void)tix;
}

// ================= fused QKV GEMM + flash attention (R13 best config) =================
#define GST 40
#define QKV_STAGE (2*128*GST)        // ushorts per stage (A|W)
#define MST 130                      // V-transpose tile stride (ushorts)
#define KST 72
#define ATT_STAGE (2*64*KST)         // ushorts per stage (K|V)
#define FUSED_SMEM 40960

__global__ __launch_bounds__(256, 2)
void fused_qkv_attn(const float* __restrict__ bq, const float* __restrict__ bk,
                    const float* __restrict__ bv, const float* __restrict__ mask,
                    float* __restrict__ out)
{
    extern __shared__ unsigned short smq[];
    const int tid = threadIdx.x, lane = tid & 31, wid = tid >> 5;
    const int g = lane >> 2, tg = lane & 3;
    const uint32_t sbase = smem_u32(smq);

    if (blockIdx.x < 768) {
        // ======== producer: one 128x128 QKV tile ========
        const int p  = blockIdx.x;
        const int hp = p / 96, t = (p % 96) / 32, my = p % 32;
        const int cx = t * 8 + hp;
        const int m0 = my * 128;
        const int c0 = t * 1024 + hp * 128;
        const int wm = wid >> 2, wn = wid & 3;

        float acc[4][4][4];
#pragma unroll
        for (int i = 0; i < 4; i++)
#pragma unroll
            for (int j = 0; j < 4; j++)
#pragma unroll
                for (int k = 0; k < 4; k++) acc[i][j][k] = 0.f;

        const int lrow = tid >> 1, lhalf = tid & 1;
        const unsigned short* gA0 = g_Ah + (size_t)(m0 + lrow) * HID + lhalf * 16;
        const unsigned short* gW0 = g_Wh + (size_t)(c0 + lrow) * HID + lhalf * 16;
        const uint32_t dOff = (uint32_t)(lrow * GST + lhalf * 16) * 2;

        const int aRow = wm * 64 + (lane & 15);
        const int aK   = (lane >> 4) * 8;
        const int bRow = wn * 32 + (lane & 7) + ((lane >> 4) << 3);
        const int bK   = ((lane >> 3) & 1) * 8;

#define QKV_ISSUE(CH, STG) do { \
    int k0 = (CH) * 32; \
    uint32_t dst = sbase + (uint32_t)(STG) * QKV_STAGE * 2 + dOff; \
    CP_ASYNC16(dst,                  gA0 + k0); \
    CP_ASYNC16(dst + 16,             gA0 + k0 + 8); \
    CP_ASYNC16(dst + 128*GST*2,      gW0 + k0); \
    CP_ASYNC16(dst + 128*GST*2 + 16, gW0 + k0 + 8); \
    CP_COMMIT; } while (0)

        QKV_ISSUE(0, 0);

        for (int ch = 0; ch < 32; ch++) {
            const int stg = ch & 1;
            CP_WAIT0;
            __syncthreads();
            if (ch < 31) QKV_ISSUE(ch + 1, stg ^ 1);

            const uint32_t base = sbase + (uint32_t)stg * QKV_STAGE * 2;
#pragma unroll
            for (int ks = 0; ks < 2; ks++) {
                uint32_t ah[4][4];
#pragma unroll
                for (int mi = 0; mi < 4; mi++) {
                    uint32_t ra = base + (uint32_t)((aRow + mi*16) * GST + ks*16 + aK) * 2;
                    ldsm_x4(ah[mi][0], ah[mi][1], ah[mi][2], ah[mi][3], ra);
                }
#pragma unroll
                for (int np = 0; np < 2; np++) {
                    uint32_t wh[4];
                    uint32_t rb = base + (uint32_t)(128*GST + (bRow + np*16) * GST + ks*16 + bK) * 2;
                    ldsm_x4(wh[0], wh[1], wh[2], wh[3], rb);
#pragma unroll
                    for (int j = 0; j < 2; j++) {
                        const int ni = np * 2 + j;
#pragma unroll
                        for (int mi = 0; mi < 4; mi++)
                            mma16816(acc[mi][ni], ah[mi], &wh[2*j]);
                    }
                }
            }
        }

        const float* bias = (t == 0) ? bq : ((t == 1) ? bk : bv);
        // Q carries 1/8 * log2(e) so consumer can use ex2 directly
        const float qsc = (t == 0) ? (0.125f * LOG2E) : 1.0f;

        if (t < 2) {
            unsigned short* outp = (t == 0) ? g_qh : g_kh;
#pragma unroll
            for (int mi = 0; mi < 4; mi++) {
#pragma unroll
                for (int ni = 0; ni < 4; ni++) {
                    int colE = c0 + wn * 32 + ni * 8 + 2 * tg;
                    int bcol = colE & 1023;
                    float b0f = bias[bcol], b1f = bias[bcol + 1];
                    int hh = (colE >> 6) & 15, dd = colE & 63;
#pragma unroll
                    for (int hr = 0; hr < 2; hr++) {
                        int row = m0 + wm * 64 + mi * 16 + g + hr * 8;
                        int s = row >> 2, b = row & 3;
                        uint32_t hv = pack2h((acc[mi][ni][hr*2+0] + b0f) * qsc,
                                             (acc[mi][ni][hr*2+1] + b1f) * qsc);
                        size_t idx = ((size_t)(b * NHEAD + hh) * S_LEN + s) * HDIM + dd;
                        *(uint32_t*)&outp[idx] = hv;
                    }
                }
            }
        } else {
            // V: transpose through smem, then coalesced [head][d][s] writes
            unsigned short* Th = smq;
            __syncthreads();
#pragma unroll
            for (int mi = 0; mi < 4; mi++) {
#pragma unroll
                for (int ni = 0; ni < 4; ni++) {
                    int col = wn * 32 + ni * 8 + 2 * tg;
                    int bcol = (c0 + col) & 1023;
                    float b0f = bias[bcol], b1f = bias[bcol + 1];
#pragma unroll
                    for (int hr = 0; hr < 2; hr++) {
                        int rloc = wm * 64 + mi * 16 + g + hr * 8;
                        Th[col * MST + rloc]       = __half_as_ushort(
                            __float2half_rn(acc[mi][ni][hr * 2 + 0] + b0f));
                        Th[(col + 1) * MST + rloc] = __half_as_ushort(
                            __float2half_rn(acc[mi][ni][hr * 2 + 1] + b1f));
                    }
                }
            }
            __syncthreads();
#pragma unroll
            for (int rep = 0; rep < 2; rep++) {
                int sid = tid + rep * 256;
                int col = sid >> 2, b = sid & 3;
                int cg = c0 + col;
                int hh = (cg >> 6) & 15, dd = cg & 63;
                size_t gb = ((size_t)(b * NHEAD + hh) * HDIM + dd) * S_LEN + (m0 >> 2);
                uint32_t uh[16];
#pragma unroll
                for (int j = 0; j < 16; j++) {
                    uh[j] = (uint32_t)Th[col * MST + (2*j) * 4 + b]
                          | ((uint32_t)Th[col * MST + (2*j + 1) * 4 + b] << 16);
                }
#pragma unroll
                for (int j = 0; j < 4; j++)
                    *(uint4*)(g_vh + gb + j * 8) = make_uint4(uh[4*j], uh[4*j+1], uh[4*j+2], uh[4*j+3]);
            }
        }

        // ---- release: publish this column tile ----
        __threadfence();
        __syncthreads();
        if (tid == 0) atomicAdd(&g_cnt[cx], 1u);

    } else {
        // ======== consumer: one attention CTA (head n, 128-q tile) ========
        const int c  = blockIdx.x - 768;
        const int hp = c >> 6, r = c & 63;
        const int h  = 2 * hp + (r & 1);
        const int b  = (r >> 1) & 3;
        const int qt = r >> 3;
        const int n  = b * NHEAD + h;

        // mask staged as half, pre-scaled by log2(e)
        unsigned short* msm = smq + 2 * ATT_STAGE;
        {
            float4 x = *(const float4*)(mask + (size_t)n * S_LEN + tid * 4);
            *(uint32_t*)&msm[tid * 4]     = pack2h(x.x * LOG2E, x.y * LOG2E);
            *(uint32_t*)&msm[tid * 4 + 2] = pack2h(x.z * LOG2E, x.w * LOG2E);
        }

        if (tid == 0) {
            while (!(*(volatile unsigned*)&g_cnt[hp]      == 32u &&
                     *(volatile unsigned*)&g_cnt[8 + hp]  == 32u &&
                     *(volatile unsigned*)&g_cnt[16 + hp] == 32u))
                __nanosleep(256);
        }
        __syncthreads();
        __threadfence();

        uint32_t aqh[4][4];
        {
            const int row = qt * 128 + wid * 16 + g;
            const unsigned short* qh = g_qh + ((size_t)n * S_LEN + row) * HDIM;
#pragma unroll
            for (int ks = 0; ks < 4; ks++) {
                int k = ks * 16 + 2 * tg;
                aqh[ks][0] = *(const uint32_t*)(qh + k);
                aqh[ks][1] = *(const uint32_t*)(qh + 8*HDIM + k);
                aqh[ks][2] = *(const uint32_t*)(qh + k + 8);
                aqh[ks][3] = *(const uint32_t*)(qh + 8*HDIM + k + 8);
            }
        }

        float oacc[8][4];
#pragma unroll
        for (int i = 0; i < 8; i++)
#pragma unroll
            for (int j = 0; j < 4; j++) oacc[i][j] = 0.f;
        float l0 = 0.f, l1 = 0.f;

        const int lrow = tid >> 2, lseg = (tid & 3) * 2;
        const unsigned short* gkh = g_kh + (size_t)n * S_LEN * HDIM;
        const unsigned short* gvh = g_vh + (size_t)n * S_LEN * HDIM + (size_t)lrow * S_LEN;
        const uint32_t dKV = (uint32_t)(lrow * KST + lseg * 8) * 2;

#define ATT_ISSUE(KT, STG) do { \
    uint32_t dst = sbase + (uint32_t)(STG) * ATT_STAGE * 2 + dKV; \
    const unsigned short* sk = gkh + ((KT)*64 + lrow) * HDIM + lseg * 8; \
    const unsigned short* sv = gvh + (KT)*64 + lseg * 8; \
    CP_ASYNC16(dst,              sk);  CP_ASYNC16(dst + 16,              sk + 8); \
    CP_ASYNC16(dst + 64*KST*2,   sv);  CP_ASYNC16(dst + 64*KST*2 + 16,   sv + 8); \
    CP_COMMIT; } while (0)

        const int bRow = (lane & 7) + ((lane >> 4) << 3);
        const int bK   = ((lane >> 3) & 1) * 8;

        ATT_ISSUE(0, 0);

        for (int kt = 0; kt < 16; kt++) {
            const int stg = kt & 1;
            CP_WAIT0;
            __syncthreads();
            if (kt < 15) ATT_ISSUE(kt + 1, stg ^ 1);

            const uint32_t base = sbase + (uint32_t)stg * ATT_STAGE * 2;

            float sacc[8][4];
#pragma unroll
            for (int i = 0; i < 8; i++)
#pragma unroll
                for (int j = 0; j < 4; j++) sacc[i][j] = 0.f;

#pragma unroll
            for (int ks = 0; ks < 4; ks++) {
#pragma unroll
                for (int np = 0; np < 4; np++) {
                    uint32_t kh[4];
                    uint32_t rb = base + (uint32_t)((np*16 + bRow) * KST + ks*16 + bK) * 2;
                    ldsm_x4(kh[0], kh[1], kh[2], kh[3], rb);
                    mma16816(sacc[np*2],   aqh[ks], &kh[0]);
                    mma16816(sacc[np*2+1], aqh[ks], &kh[2]);
                }
            }

            // ---- half2 softmax: p = ex2(s + mask') ----
            uint32_t ph[8][2];
            uint32_t ls0 = 0u, ls1 = 0u;
#pragma unroll
            for (int ni = 0; ni < 8; ni++) {
                uint32_t mk2 = *(const uint32_t*)&msm[kt*64 + ni*8 + 2*tg];
                uint32_t s01 = hadd2u(pack2h(sacc[ni][0], sacc[ni][1]), mk2);
                uint32_t s23 = hadd2u(pack2h(sacc[ni][2], sacc[ni][3]), mk2);
                uint32_t p01 = ex2_h2(s01);
                uint32_t p23 = ex2_h2(s23);
                ph[ni][0] = p01;
                ph[ni][1] = p23;
                ls0 = hadd2u(ls0, p01);
                ls1 = hadd2u(ls1, p23);
            }
            l0 += h2sum(ls0);
            l1 += h2sum(ls1);

            // ---- AV: P half2 registers feed the MMA directly ----
#pragma unroll
            for (int kk = 0; kk < 4; kk++) {
                uint32_t pah[4];
                pah[0] = ph[2*kk][0];
                pah[1] = ph[2*kk][1];
                pah[2] = ph[2*kk+1][0];
                pah[3] = ph[2*kk+1][1];
#pragma unroll
                for (int np = 0; np < 4; np++) {
                    uint32_t vh[4];
                    uint32_t rb = base + (uint32_t)(64*KST + (np*16 + bRow) * KST + kk*16 + bK) * 2;
                    ldsm_x4(vh[0], vh[1], vh[2], vh[3], rb);
                    mma16816(oacc[np*2],   pah, &vh[0]);
                    mma16816(oacc[np*2+1], pah, &vh[2]);
                }
            }
        }

        // ---- one-time denominator reduction across the quad ----
        l0 += __shfl_xor_sync(0xffffffffu, l0, 1);
        l0 += __shfl_xor_sync(0xffffffffu, l0, 2);
        l1 += __shfl_xor_sync(0xffffffffu, l1, 1);
        l1 += __shfl_xor_sync(0xffffffffu, l1, 2);

        const float inv0 = 1.f / l0, inv1 = 1.f / l1;
        const int row0 = qt * 128 + wid * 16 + g;
#pragma unroll
        for (int ni = 0; ni < 8; ni++) {
            int d = ni * 8 + 2 * tg;
            float2 v0 = make_float2(oacc[ni][0] * inv0, oacc[ni][1] * inv0);
            float2 v1 = make_float2(oacc[ni][2] * inv1, oacc[ni][3] * inv1);
            *(float2*)(out + (size_t)row0 * (BATCH*HID) + b * HID + h * HDIM + d) = v0;
            *(float2*)(out + (size_t)(row0 + 8) * (BATCH*HID) + b * HID + h * HDIM + d) = v1;
        }
    }
}

// ------------------------------------------------------------------
extern "C" void kernel_launch(void* const* d_in, const int* in_sizes, int n_in,
                              void* d_out, int out_size)
{
    const float* hs   = (const float*)d_in[0];
    const float* mask = (const float*)d_in[1];
    const float* Wq   = (const float*)d_in[2];
    const float* bq   = (const float*)d_in[3];
    const float* Wk   = (const float*)d_in[4];
    const float* bk   = (const float*)d_in[5];
    const float* Wv   = (const float*)d_in[6];
    const float* bv   = (const float*)d_in[7];
    float* out = (float*)d_out;

    cvt_all<<<1792, 256>>>(hs, Wq, Wk, Wv);   // 1792*4096 = 7,340,032 elements exact

    cudaFuncSetAttribute(fused_qkv_attn, cudaFuncAttributeMaxDynamicSharedMemorySize,
                         FUSED_SMEM);
    fused_qkv_attn<<<1280, 256, FUSED_SMEM>>>(bq, bk, bv, mask, out);
}